// round 3
// baseline (speedup 1.0000x reference)
#include <cuda_runtime.h>
#include <cuda_bf16.h>

#define N_USER 100000
#define N_NODES 200000
#define NNZ 6400000
#define EMB 64
#define BATCH 1024

typedef unsigned long long u64;

// ---------------- scratch (device globals; no allocation allowed) ----------
__device__ int   g_rowptr[N_NODES + 1];
__device__ float g_ego[2][(size_t)N_NODES * EMB];   // ping-pong ego buffers
__device__ float g_side[(size_t)N_NODES * EMB];
__device__ float g_prod[(size_t)N_NODES * EMB];

// ---------------- packed f32x2 helpers (FFMA2: only reachable via PTX) -----
__device__ __forceinline__ u64 pk2(float x, float y) {
    u64 r; asm("mov.b64 %0,{%1,%2};" : "=l"(r) : "f"(x), "f"(y)); return r;
}
__device__ __forceinline__ float2 upk(u64 a) {
    float2 f; asm("mov.b64 {%0,%1},%2;" : "=f"(f.x), "=f"(f.y) : "l"(a)); return f;
}
__device__ __forceinline__ u64 ffma2(u64 a, u64 b, u64 c) {
    u64 d; asm("fma.rn.f32x2 %0,%1,%2,%3;" : "=l"(d) : "l"(a), "l"(b), "l"(c)); return d;
}

// ---------------- 1) CSR row_ptr from sorted COO rows ----------------------
__global__ void build_rowptr(const int* __restrict__ row) {
    int r = blockIdx.x * blockDim.x + threadIdx.x;
    if (r > N_NODES) return;
    int lo = 0, hi = NNZ;
    while (lo < hi) {
        int mid = (lo + hi) >> 1;
        if (row[mid] < r) lo = mid + 1; else hi = mid;
    }
    g_rowptr[r] = lo;
}

// ---------------- 2) output slice 0 (raw embeddings, gathered) -------------
__global__ void init_out(const int* __restrict__ users, const int* __restrict__ pos,
                         const int* __restrict__ neg,
                         const float* __restrict__ uemb, const float* __restrict__ iemb,
                         float* __restrict__ out) {
    int wid  = (blockIdx.x * blockDim.x + threadIdx.x) >> 5;
    int lane = threadIdx.x & 31;
    if (wid >= 3 * BATCH) return;
    int g = wid / BATCH, b = wid - g * BATCH;
    const float* src;
    if (g == 0)      src = uemb + (size_t)users[b] * EMB;
    else if (g == 1) src = iemb + (size_t)pos[b]   * EMB;
    else             src = iemb + (size_t)neg[b]   * EMB;
    float2 v = *reinterpret_cast<const float2*>(src + 2 * lane);
    *reinterpret_cast<float2*>(out + (size_t)wid * 256 + 2 * lane) = v;
}

// ---------------- 3) SpMM: side = A @ ego ; emit side[], prod[] ------------
// Warp per row. Half-warp (16 lanes) per nnz; lane owns a dim quad via float4.
// 8 LDG.128 batched in flight (16 nnz) for MLP.
template<bool SPLIT>
__global__ void __launch_bounds__(256) spmm_kernel(
        const int* __restrict__ col, const float* __restrict__ val,
        int src, const float* __restrict__ uemb, const float* __restrict__ iemb) {
    __shared__ float2 stage[8][32];
    const float* __restrict__ base = g_ego[src];
    int w = threadIdx.x >> 5, lane = threadIdx.x & 31;
    int h = lane >> 4, q = lane & 15;          // half index, dim quad
    int r = blockIdx.x * 8 + w;
    int beg = g_rowptr[r], end = g_rowptr[r + 1];
    float4 acc = make_float4(0.f, 0.f, 0.f, 0.f);

    for (int bs = beg; bs < end; bs += 32) {
        int i = bs + lane;
        if (i < end) stage[w][lane] = make_float2(val[i], __int_as_float(col[i]));
        __syncwarp();
        int cnt = min(32, end - bs);
        int j = 0;
        // main: 16 nnz per iter, 8 LDG.128 in flight per half
        for (; j + 16 <= cnt; j += 16) {
            float4 x[8]; float v[8];
            #pragma unroll
            for (int t = 0; t < 8; t++) {
                float2 cv = stage[w][j + 2 * t + h];
                v[t] = cv.x;
                int c = __float_as_int(cv.y);
                const float* p;
                if (SPLIT) p = (c < N_USER) ? uemb + (size_t)c * EMB
                                            : iemb + (size_t)(c - N_USER) * EMB;
                else       p = base + (size_t)c * EMB;
                x[t] = *reinterpret_cast<const float4*>(p + 4 * q);
            }
            #pragma unroll
            for (int t = 0; t < 8; t++) {
                acc.x = fmaf(v[t], x[t].x, acc.x);
                acc.y = fmaf(v[t], x[t].y, acc.y);
                acc.z = fmaf(v[t], x[t].z, acc.z);
                acc.w = fmaf(v[t], x[t].w, acc.w);
            }
        }
        // pairs
        for (; j + 2 <= cnt; j += 2) {
            float2 cv = stage[w][j + h];
            float v = cv.x;
            int c = __float_as_int(cv.y);
            const float* p;
            if (SPLIT) p = (c < N_USER) ? uemb + (size_t)c * EMB
                                        : iemb + (size_t)(c - N_USER) * EMB;
            else       p = base + (size_t)c * EMB;
            float4 x = *reinterpret_cast<const float4*>(p + 4 * q);
            acc.x = fmaf(v, x.x, acc.x); acc.y = fmaf(v, x.y, acc.y);
            acc.z = fmaf(v, x.z, acc.z); acc.w = fmaf(v, x.w, acc.w);
        }
        // odd leftover: half 0 only
        if (j < cnt && h == 0) {
            float2 cv = stage[w][j];
            float v = cv.x;
            int c = __float_as_int(cv.y);
            const float* p;
            if (SPLIT) p = (c < N_USER) ? uemb + (size_t)c * EMB
                                        : iemb + (size_t)(c - N_USER) * EMB;
            else       p = base + (size_t)c * EMB;
            float4 x = *reinterpret_cast<const float4*>(p + 4 * q);
            acc.x = fmaf(v, x.x, acc.x); acc.y = fmaf(v, x.y, acc.y);
            acc.z = fmaf(v, x.z, acc.z); acc.w = fmaf(v, x.w, acc.w);
        }
        __syncwarp();
    }
    // merge the two halves
    acc.x += __shfl_xor_sync(0xffffffffu, acc.x, 16);
    acc.y += __shfl_xor_sync(0xffffffffu, acc.y, 16);
    acc.z += __shfl_xor_sync(0xffffffffu, acc.z, 16);
    acc.w += __shfl_xor_sync(0xffffffffu, acc.w, 16);

    if (h == 0) {
        *reinterpret_cast<float4*>(g_side + (size_t)r * EMB + 4 * q) = acc;
    } else {
        const float* pr;
        if (SPLIT) pr = (r < N_USER) ? uemb + (size_t)r * EMB
                                     : iemb + (size_t)(r - N_USER) * EMB;
        else       pr = base + (size_t)r * EMB;
        float4 e = *reinterpret_cast<const float4*>(pr + 4 * q);
        float4 o = make_float4(e.x * acc.x, e.y * acc.y, e.z * acc.z, e.w * acc.w);
        *reinterpret_cast<float4*>(g_prod + (size_t)r * EMB + 4 * q) = o;
    }
}

// ---------------- 4) dense: ego_next = leaky(side@Wgc + prod@Wbi + b) ------
// 64 rows/block, warp owns 8 rows, lane owns out-dims (2*lane, 2*lane+1).
// FFMA2 packs k-pairs: a=(s_2k,s_2k+1) straight from smem, b=W^T pair regs.
__global__ void __launch_bounds__(256, 2) dense_kernel(
        const float* __restrict__ Wgc, const float* __restrict__ bgc,
        const float* __restrict__ Wbi, const float* __restrict__ bbi,
        int dst) {
    __shared__ __align__(16) float s_side[64][EMB];   // 16 KB
    __shared__ __align__(16) float s_prod[64][EMB];   // 16 KB
    float* __restrict__ ego_next = g_ego[dst];
    int tid = threadIdx.x, w = tid >> 5, lane = tid & 31;
    int rowbase = blockIdx.x * 64;

    // stage 64 rows of side/prod (coalesced float4)
    const float4* s4 = reinterpret_cast<const float4*>(g_side + (size_t)rowbase * EMB);
    const float4* p4 = reinterpret_cast<const float4*>(g_prod + (size_t)rowbase * EMB);
    float4* ss = reinterpret_cast<float4*>(&s_side[0][0]);
    float4* pp = reinterpret_cast<float4*>(&s_prod[0][0]);
    #pragma unroll
    for (int i = 0; i < 4; i++) {
        ss[tid + i * 256] = s4[tid + i * 256];
        pp[tid + i * 256] = p4[tid + i * 256];
    }
    __syncthreads();

    const int d0 = 2 * lane;
    const int r0 = w * 8;
    u64 ag0[8], ag1[8], ab0[8], ab1[8];
    #pragma unroll
    for (int r = 0; r < 8; r++) { ag0[r] = 0; ag1[r] = 0; ab0[r] = 0; ab1[r] = 0; }

    #pragma unroll
    for (int c = 0; c < 8; c++) {                 // 8 chunks x 4 k-pairs
        u64 wg0[4], wg1[4], wb0[4], wb1[4];
        #pragma unroll
        for (int t = 0; t < 4; t++) {
            int k = (c * 4 + t) * 2;
            wg0[t] = pk2(Wgc[k * EMB + d0],     Wgc[(k + 1) * EMB + d0]);
            wg1[t] = pk2(Wgc[k * EMB + d0 + 1], Wgc[(k + 1) * EMB + d0 + 1]);
            wb0[t] = pk2(Wbi[k * EMB + d0],     Wbi[(k + 1) * EMB + d0]);
            wb1[t] = pk2(Wbi[k * EMB + d0 + 1], Wbi[(k + 1) * EMB + d0 + 1]);
        }
        #pragma unroll
        for (int r = 0; r < 8; r++) {
            #pragma unroll
            for (int t = 0; t < 4; t++) {
                int k = (c * 4 + t) * 2;
                u64 sv = *reinterpret_cast<const u64*>(&s_side[r0 + r][k]);  // broadcast
                u64 pv = *reinterpret_cast<const u64*>(&s_prod[r0 + r][k]);
                ag0[r] = ffma2(sv, wg0[t], ag0[r]);
                ag1[r] = ffma2(sv, wg1[t], ag1[r]);
                ab0[r] = ffma2(pv, wb0[t], ab0[r]);
                ab1[r] = ffma2(pv, wb1[t], ab1[r]);
            }
        }
    }

    float2 bgv = *reinterpret_cast<const float2*>(bgc + d0);
    float2 bbv = *reinterpret_cast<const float2*>(bbi + d0);
    #pragma unroll
    for (int r = 0; r < 8; r++) {
        float2 g0 = upk(ag0[r]), g1 = upk(ag1[r]);
        float2 b0 = upk(ab0[r]), b1 = upk(ab1[r]);
        float x = (g0.x + g0.y) + (b0.x + b0.y) + bgv.x + bbv.x;
        float y = (g1.x + g1.y) + (b1.x + b1.y) + bgv.y + bbv.y;
        x = x > 0.f ? x : 0.2f * x;
        y = y > 0.f ? y : 0.2f * y;
        *reinterpret_cast<float2*>(ego_next + (size_t)(rowbase + r0 + r) * EMB + d0)
            = make_float2(x, y);
    }
}

// ---------------- 5) per-layer gather + l2norm straight into d_out ---------
__global__ void gather_norm(const int* __restrict__ users, const int* __restrict__ pos,
                            const int* __restrict__ neg, int src, float* __restrict__ out,
                            int slice) {
    const float* __restrict__ ego = g_ego[src];
    int wid  = (blockIdx.x * blockDim.x + threadIdx.x) >> 5;
    int lane = threadIdx.x & 31;
    if (wid >= 3 * BATCH) return;
    int g = wid / BATCH, b = wid - g * BATCH;
    int node;
    if (g == 0)      node = users[b];
    else if (g == 1) node = N_USER + pos[b];
    else             node = N_USER + neg[b];
    float2 v = *reinterpret_cast<const float2*>(ego + (size_t)node * EMB + 2 * lane);
    float ss = v.x * v.x + v.y * v.y;
    #pragma unroll
    for (int o = 16; o; o >>= 1) ss += __shfl_xor_sync(0xffffffffu, ss, o);
    float n = sqrtf(ss);
    float inv = 1.f / fmaxf(n, 1e-12f);
    *reinterpret_cast<float2*>(out + (size_t)wid * 256 + slice * EMB + 2 * lane)
        = make_float2(v.x * inv, v.y * inv);
}

// ---------------- launch ---------------------------------------------------
extern "C" void kernel_launch(void* const* d_in, const int* in_sizes, int n_in,
                              void* d_out, int out_size) {
    const int*   users = (const int*)  d_in[0];
    const int*   pos   = (const int*)  d_in[1];
    const int*   neg   = (const int*)  d_in[2];
    const int*   arow  = (const int*)  d_in[3];
    const int*   acol  = (const int*)  d_in[4];
    const float* aval  = (const float*)d_in[5];
    const float* uemb  = (const float*)d_in[6];
    const float* iemb  = (const float*)d_in[7];
    const float* Wgc[3] = { (const float*)d_in[8],  (const float*)d_in[12], (const float*)d_in[16] };
    const float* bgc[3] = { (const float*)d_in[9],  (const float*)d_in[13], (const float*)d_in[17] };
    const float* Wbi[3] = { (const float*)d_in[10], (const float*)d_in[14], (const float*)d_in[18] };
    const float* bbi[3] = { (const float*)d_in[11], (const float*)d_in[15], (const float*)d_in[19] };
    float* out = (float*)d_out;

    build_rowptr<<<(N_NODES + 256) / 256, 256>>>(arow);
    init_out<<<(3 * BATCH * 32) / 256, 256>>>(users, pos, neg, uemb, iemb, out);

    // layer 0: gather straight from user/item embeddings (no concat copy)
    spmm_kernel<true><<<N_NODES / 8, 256>>>(acol, aval, 0, uemb, iemb);
    dense_kernel<<<N_NODES / 64, 256>>>(Wgc[0], bgc[0], Wbi[0], bbi[0], 0);
    gather_norm<<<(3 * BATCH * 32) / 256, 256>>>(users, pos, neg, 0, out, 1);

    // layer 1
    spmm_kernel<false><<<N_NODES / 8, 256>>>(acol, aval, 0, uemb, iemb);
    dense_kernel<<<N_NODES / 64, 256>>>(Wgc[1], bgc[1], Wbi[1], bbi[1], 1);
    gather_norm<<<(3 * BATCH * 32) / 256, 256>>>(users, pos, neg, 1, out, 2);

    // layer 2
    spmm_kernel<false><<<N_NODES / 8, 256>>>(acol, aval, 1, uemb, iemb);
    dense_kernel<<<N_NODES / 64, 256>>>(Wgc[2], bgc[2], Wbi[2], bbi[2], 0);
    gather_norm<<<(3 * BATCH * 32) / 256, 256>>>(users, pos, neg, 0, out, 3);
}

// round 5
// speedup vs baseline: 1.1450x; 1.1450x over previous
#include <cuda_runtime.h>
#include <cuda_fp16.h>

#define N_USER 100000
#define N_NODES 200000
#define NNZ 6400000
#define EMB 64
#define BATCH 1024

typedef unsigned long long u64;

// ---------------- scratch (device globals; no allocation allowed) ----------
__device__ int    g_rowptr[N_NODES + 1];
__device__ float  g_ego[2][(size_t)N_NODES * EMB];    // fp32 ping-pong (output path)
__device__ __half g_egoh[2][(size_t)N_NODES * EMB];   // fp16 mirror (gather path)
__device__ float  g_side[(size_t)N_NODES * EMB];
__device__ float  g_prod[(size_t)N_NODES * EMB];

// ---------------- packed f32x2 helpers (FFMA2: only reachable via PTX) -----
__device__ __forceinline__ u64 pk2(float x, float y) {
    u64 r; asm("mov.b64 %0,{%1,%2};" : "=l"(r) : "f"(x), "f"(y)); return r;
}
__device__ __forceinline__ float2 upk(u64 a) {
    float2 f; asm("mov.b64 {%0,%1},%2;" : "=f"(f.x), "=f"(f.y) : "l"(a)); return f;
}
__device__ __forceinline__ u64 ffma2(u64 a, u64 b, u64 c) {
    u64 d; asm("fma.rn.f32x2 %0,%1,%2,%3;" : "=l"(d) : "l"(a), "l"(b), "l"(c)); return d;
}

// ---------------- 1) CSR row_ptr from sorted COO rows ----------------------
__global__ void build_rowptr(const int* __restrict__ row) {
    int r = blockIdx.x * blockDim.x + threadIdx.x;
    if (r > N_NODES) return;
    int lo = 0, hi = NNZ;
    while (lo < hi) {
        int mid = (lo + hi) >> 1;
        if (row[mid] < r) lo = mid + 1; else hi = mid;
    }
    g_rowptr[r] = lo;
}

// ---------------- 2) fp16 copy of ego0 = concat(user_emb, item_emb) --------
__global__ void conv_ego0(const float4* __restrict__ u, const float4* __restrict__ it) {
    int i = blockIdx.x * blockDim.x + threadIdx.x;     // one float4 (4 elems)
    const int NU4 = N_USER * EMB / 4;
    const int NT4 = N_NODES * EMB / 4;
    if (i >= NT4) return;
    float4 v = (i < NU4) ? u[i] : it[i - NU4];
    half2 h0 = __floats2half2_rn(v.x, v.y);
    half2 h1 = __floats2half2_rn(v.z, v.w);
    uint2 pk;
    pk.x = *reinterpret_cast<unsigned*>(&h0);
    pk.y = *reinterpret_cast<unsigned*>(&h1);
    reinterpret_cast<uint2*>(g_egoh[0])[i] = pk;
}

// ---------------- 3) output slice 0 (raw embeddings, gathered) -------------
__global__ void init_out(const int* __restrict__ users, const int* __restrict__ pos,
                         const int* __restrict__ neg,
                         const float* __restrict__ uemb, const float* __restrict__ iemb,
                         float* __restrict__ out) {
    int wid  = (blockIdx.x * blockDim.x + threadIdx.x) >> 5;
    int lane = threadIdx.x & 31;
    if (wid >= 3 * BATCH) return;
    int g = wid / BATCH, b = wid - g * BATCH;
    const float* src;
    if (g == 0)      src = uemb + (size_t)users[b] * EMB;
    else if (g == 1) src = iemb + (size_t)pos[b]   * EMB;
    else             src = iemb + (size_t)neg[b]   * EMB;
    float2 v = *reinterpret_cast<const float2*>(src + 2 * lane);
    *reinterpret_cast<float2*>(out + (size_t)wid * 256 + 2 * lane) = v;
}

// ---------------- 4) SpMM over fp16 ego: side = A @ ego ; prod = ego*side --
// Warp per row. Half-warp per nnz; lane owns a dim quad (4 halves = LDG.64).
__device__ __forceinline__ void fma_quad(float4& acc, float v, uint2 raw) {
    float2 f0 = __half22float2(*reinterpret_cast<half2*>(&raw.x));
    float2 f1 = __half22float2(*reinterpret_cast<half2*>(&raw.y));
    acc.x = fmaf(v, f0.x, acc.x); acc.y = fmaf(v, f0.y, acc.y);
    acc.z = fmaf(v, f1.x, acc.z); acc.w = fmaf(v, f1.y, acc.w);
}

__global__ void __launch_bounds__(256) spmm_kernel(
        const int* __restrict__ col, const float* __restrict__ val, int src) {
    __shared__ float2 stage[8][32];
    const __half* __restrict__ ego = g_egoh[src];
    int w = threadIdx.x >> 5, lane = threadIdx.x & 31;
    int h = lane >> 4, q = lane & 15;          // half index, dim quad
    int r = blockIdx.x * 8 + w;
    int beg = g_rowptr[r], end = g_rowptr[r + 1];
    float4 acc = make_float4(0.f, 0.f, 0.f, 0.f);

    for (int bs = beg; bs < end; bs += 32) {
        int i = bs + lane;
        if (i < end) stage[w][lane] = make_float2(val[i], __int_as_float(col[i]));
        __syncwarp();
        int cnt = min(32, end - bs);
        int j = 0;
        for (; j + 16 <= cnt; j += 16) {       // 16 nnz, 8 LDG.64 in flight/half
            uint2 raw[8]; float v[8];
            #pragma unroll
            for (int t = 0; t < 8; t++) {
                float2 cv = stage[w][j + 2 * t + h];
                v[t] = cv.x;
                int c = __float_as_int(cv.y);
                raw[t] = *reinterpret_cast<const uint2*>(ego + (size_t)c * EMB + 4 * q);
            }
            #pragma unroll
            for (int t = 0; t < 8; t++) fma_quad(acc, v[t], raw[t]);
        }
        for (; j + 2 <= cnt; j += 2) {
            float2 cv = stage[w][j + h];
            int c = __float_as_int(cv.y);
            uint2 raw = *reinterpret_cast<const uint2*>(ego + (size_t)c * EMB + 4 * q);
            fma_quad(acc, cv.x, raw);
        }
        if (j < cnt && h == 0) {
            float2 cv = stage[w][j];
            int c = __float_as_int(cv.y);
            uint2 raw = *reinterpret_cast<const uint2*>(ego + (size_t)c * EMB + 4 * q);
            fma_quad(acc, cv.x, raw);
        }
        __syncwarp();
    }
    acc.x += __shfl_xor_sync(0xffffffffu, acc.x, 16);
    acc.y += __shfl_xor_sync(0xffffffffu, acc.y, 16);
    acc.z += __shfl_xor_sync(0xffffffffu, acc.z, 16);
    acc.w += __shfl_xor_sync(0xffffffffu, acc.w, 16);

    if (h == 0) {
        *reinterpret_cast<float4*>(g_side + (size_t)r * EMB + 4 * q) = acc;
    } else {
        uint2 raw = *reinterpret_cast<const uint2*>(ego + (size_t)r * EMB + 4 * q);
        float2 f0 = __half22float2(*reinterpret_cast<half2*>(&raw.x));
        float2 f1 = __half22float2(*reinterpret_cast<half2*>(&raw.y));
        float4 o = make_float4(f0.x * acc.x, f0.y * acc.y, f1.x * acc.z, f1.y * acc.w);
        *reinterpret_cast<float4*>(g_prod + (size_t)r * EMB + 4 * q) = o;
    }
}

// ---------------- 5) dense: ego_next = leaky(side@Wgc + prod@Wbi + b) ------
// 64 rows/block, warp owns 8 rows, lane owns out-dims (2*lane, 2*lane+1).
// LDS.128 loads a k-quad (2 packed pairs); each broadcast load feeds 4 FFMA2.
__global__ void __launch_bounds__(256, 2) dense_kernel(
        const float* __restrict__ Wgc, const float* __restrict__ bgc,
        const float* __restrict__ Wbi, const float* __restrict__ bbi,
        int dst) {
    __shared__ __align__(16) float s_side[64][EMB];   // 16 KB
    __shared__ __align__(16) float s_prod[64][EMB];   // 16 KB
    float*  __restrict__ ego_next  = g_ego[dst];
    __half* __restrict__ egoh_next = g_egoh[dst];
    int tid = threadIdx.x, w = tid >> 5, lane = tid & 31;
    int rowbase = blockIdx.x * 64;

    const float4* s4 = reinterpret_cast<const float4*>(g_side + (size_t)rowbase * EMB);
    const float4* p4 = reinterpret_cast<const float4*>(g_prod + (size_t)rowbase * EMB);
    float4* ss = reinterpret_cast<float4*>(&s_side[0][0]);
    float4* pp = reinterpret_cast<float4*>(&s_prod[0][0]);
    #pragma unroll
    for (int i = 0; i < 4; i++) {
        ss[tid + i * 256] = s4[tid + i * 256];
        pp[tid + i * 256] = p4[tid + i * 256];
    }
    __syncthreads();

    const int d0 = 2 * lane;
    const int r0 = w * 8;
    u64 ag0[8], ag1[8], ab0[8], ab1[8];
    #pragma unroll
    for (int r = 0; r < 8; r++) { ag0[r] = 0; ag1[r] = 0; ab0[r] = 0; ab1[r] = 0; }

    #pragma unroll
    for (int c = 0; c < 8; c++) {                 // 8 k-values per chunk
        u64 wg0[4], wg1[4], wb0[4], wb1[4];
        #pragma unroll
        for (int t = 0; t < 4; t++) {
            int k = c * 8 + 2 * t;
            wg0[t] = pk2(Wgc[k * EMB + d0],     Wgc[(k + 1) * EMB + d0]);
            wg1[t] = pk2(Wgc[k * EMB + d0 + 1], Wgc[(k + 1) * EMB + d0 + 1]);
            wb0[t] = pk2(Wbi[k * EMB + d0],     Wbi[(k + 1) * EMB + d0]);
            wb1[t] = pk2(Wbi[k * EMB + d0 + 1], Wbi[(k + 1) * EMB + d0 + 1]);
        }
        #pragma unroll
        for (int r = 0; r < 8; r++) {
            float4 s01 = *reinterpret_cast<const float4*>(&s_side[r0 + r][c * 8]);
            float4 s23 = *reinterpret_cast<const float4*>(&s_side[r0 + r][c * 8 + 4]);
            float4 p01 = *reinterpret_cast<const float4*>(&s_prod[r0 + r][c * 8]);
            float4 p23 = *reinterpret_cast<const float4*>(&s_prod[r0 + r][c * 8 + 4]);
            u64 sv[4], pv[4];
            sv[0] = reinterpret_cast<const u64*>(&s01)[0];
            sv[1] = reinterpret_cast<const u64*>(&s01)[1];
            sv[2] = reinterpret_cast<const u64*>(&s23)[0];
            sv[3] = reinterpret_cast<const u64*>(&s23)[1];
            pv[0] = reinterpret_cast<const u64*>(&p01)[0];
            pv[1] = reinterpret_cast<const u64*>(&p01)[1];
            pv[2] = reinterpret_cast<const u64*>(&p23)[0];
            pv[3] = reinterpret_cast<const u64*>(&p23)[1];
            #pragma unroll
            for (int t = 0; t < 4; t++) {
                ag0[r] = ffma2(sv[t], wg0[t], ag0[r]);
                ag1[r] = ffma2(sv[t], wg1[t], ag1[r]);
                ab0[r] = ffma2(pv[t], wb0[t], ab0[r]);
                ab1[r] = ffma2(pv[t], wb1[t], ab1[r]);
            }
        }
    }

    float2 bgv = *reinterpret_cast<const float2*>(bgc + d0);
    float2 bbv = *reinterpret_cast<const float2*>(bbi + d0);
    #pragma unroll
    for (int r = 0; r < 8; r++) {
        float2 g0 = upk(ag0[r]), g1 = upk(ag1[r]);
        float2 b0 = upk(ab0[r]), b1 = upk(ab1[r]);
        float x = (g0.x + g0.y) + (b0.x + b0.y) + bgv.x + bbv.x;
        float y = (g1.x + g1.y) + (b1.x + b1.y) + bgv.y + bbv.y;
        x = x > 0.f ? x : 0.2f * x;
        y = y > 0.f ? y : 0.2f * y;
        size_t off = (size_t)(rowbase + r0 + r) * EMB + d0;
        *reinterpret_cast<float2*>(ego_next + off) = make_float2(x, y);
        half2 hx = __floats2half2_rn(x, y);
        *reinterpret_cast<half2*>(egoh_next + off) = hx;
    }
}

// ---------------- 6) per-layer gather + l2norm straight into d_out ---------
__global__ void gather_norm(const int* __restrict__ users, const int* __restrict__ pos,
                            const int* __restrict__ neg, int src, float* __restrict__ out,
                            int slice) {
    const float* __restrict__ ego = g_ego[src];
    int wid  = (blockIdx.x * blockDim.x + threadIdx.x) >> 5;
    int lane = threadIdx.x & 31;
    if (wid >= 3 * BATCH) return;
    int g = wid / BATCH, b = wid - g * BATCH;
    int node;
    if (g == 0)      node = users[b];
    else if (g == 1) node = N_USER + pos[b];
    else             node = N_USER + neg[b];
    float2 v = *reinterpret_cast<const float2*>(ego + (size_t)node * EMB + 2 * lane);
    float ss = v.x * v.x + v.y * v.y;
    #pragma unroll
    for (int o = 16; o; o >>= 1) ss += __shfl_xor_sync(0xffffffffu, ss, o);
    float n = sqrtf(ss);
    float inv = 1.f / fmaxf(n, 1e-12f);
    *reinterpret_cast<float2*>(out + (size_t)wid * 256 + slice * EMB + 2 * lane)
        = make_float2(v.x * inv, v.y * inv);
}

// ---------------- launch ---------------------------------------------------
extern "C" void kernel_launch(void* const* d_in, const int* in_sizes, int n_in,
                              void* d_out, int out_size) {
    const int*   users = (const int*)  d_in[0];
    const int*   pos   = (const int*)  d_in[1];
    const int*   neg   = (const int*)  d_in[2];
    const int*   arow  = (const int*)  d_in[3];
    const int*   acol  = (const int*)  d_in[4];
    const float* aval  = (const float*)d_in[5];
    const float* uemb  = (const float*)d_in[6];
    const float* iemb  = (const float*)d_in[7];
    const float* Wgc[3] = { (const float*)d_in[8],  (const float*)d_in[12], (const float*)d_in[16] };
    const float* bgc[3] = { (const float*)d_in[9],  (const float*)d_in[13], (const float*)d_in[17] };
    const float* Wbi[3] = { (const float*)d_in[10], (const float*)d_in[14], (const float*)d_in[18] };
    const float* bbi[3] = { (const float*)d_in[11], (const float*)d_in[15], (const float*)d_in[19] };
    float* out = (float*)d_out;

    build_rowptr<<<(N_NODES + 256) / 256, 256>>>(arow);
    conv_ego0<<<(N_NODES * EMB / 4 + 255) / 256, 256>>>(
        (const float4*)uemb, (const float4*)iemb);
    init_out<<<(3 * BATCH * 32) / 256, 256>>>(users, pos, neg, uemb, iemb, out);

    // layer 0: egoh[0] -> ego/egoh[1]
    spmm_kernel<<<N_NODES / 8, 256>>>(acol, aval, 0);
    dense_kernel<<<N_NODES / 64, 256>>>(Wgc[0], bgc[0], Wbi[0], bbi[0], 1);
    gather_norm<<<(3 * BATCH * 32) / 256, 256>>>(users, pos, neg, 1, out, 1);

    // layer 1: egoh[1] -> ego/egoh[0]
    spmm_kernel<<<N_NODES / 8, 256>>>(acol, aval, 1);
    dense_kernel<<<N_NODES / 64, 256>>>(Wgc[1], bgc[1], Wbi[1], bbi[1], 0);
    gather_norm<<<(3 * BATCH * 32) / 256, 256>>>(users, pos, neg, 0, out, 2);

    // layer 2: egoh[0] -> ego/egoh[1]
    spmm_kernel<<<N_NODES / 8, 256>>>(acol, aval, 0);
    dense_kernel<<<N_NODES / 64, 256>>>(Wgc[2], bgc[2], Wbi[2], bbi[2], 1);
    gather_norm<<<(3 * BATCH * 32) / 256, 256>>>(users, pos, neg, 1, out, 3);
}

// round 6
// speedup vs baseline: 1.7643x; 1.5408x over previous
#include <cuda_runtime.h>
#include <cuda_fp16.h>

#define N_USER 100000
#define N_NODES 200000
#define NNZ 6400000
#define EMB 64
#define BATCH 1024

// ---------------- scratch (device globals; no allocation allowed) ----------
__device__ int    g_rowptr[N_NODES + 1];
__device__ float  g_ego[2][(size_t)N_NODES * EMB];    // fp32 (output path)
__device__ __half g_egoh[2][(size_t)N_NODES * EMB];   // fp16 mirror (gather path)
__device__ __half g_sideh[(size_t)N_NODES * EMB];
__device__ __half g_prodh[(size_t)N_NODES * EMB];
__device__ __half g_wh[3][128 * EMB];                 // [Wgc;Wbi] fp16, row-major (k,n)
__device__ float  g_bias[3][EMB];                     // bgc + bbi

// ---------------- 1) CSR row_ptr from sorted COO rows ----------------------
__global__ void build_rowptr(const int* __restrict__ row) {
    int r = blockIdx.x * blockDim.x + threadIdx.x;
    if (r > N_NODES) return;
    int lo = 0, hi = NNZ;
    while (lo < hi) {
        int mid = (lo + hi) >> 1;
        if (row[mid] < r) lo = mid + 1; else hi = mid;
    }
    g_rowptr[r] = lo;
}

// ---------------- 2) fp16 ego0 + fp16 weights + fused bias -----------------
__global__ void conv_ego0(const float4* __restrict__ u, const float4* __restrict__ it) {
    int i = blockIdx.x * blockDim.x + threadIdx.x;
    const int NU4 = N_USER * EMB / 4;
    const int NT4 = N_NODES * EMB / 4;
    if (i >= NT4) return;
    float4 v = (i < NU4) ? u[i] : it[i - NU4];
    half2 h0 = __floats2half2_rn(v.x, v.y);
    half2 h1 = __floats2half2_rn(v.z, v.w);
    uint2 pk;
    pk.x = *reinterpret_cast<unsigned*>(&h0);
    pk.y = *reinterpret_cast<unsigned*>(&h1);
    reinterpret_cast<uint2*>(g_egoh[0])[i] = pk;
}

__global__ void conv_weights(const float* Wg0, const float* Wb0, const float* bg0, const float* bb0,
                             const float* Wg1, const float* Wb1, const float* bg1, const float* bb1,
                             const float* Wg2, const float* Wb2, const float* bg2, const float* bb2) {
    const float* Wg[3] = {Wg0, Wg1, Wg2};
    const float* Wb[3] = {Wb0, Wb1, Wb2};
    const float* bg[3] = {bg0, bg1, bg2};
    const float* bb[3] = {bb0, bb1, bb2};
    int i = blockIdx.x * blockDim.x + threadIdx.x;
    if (i < 3 * 128 * EMB) {
        int l = i / (128 * EMB), rem = i % (128 * EMB);
        int k = rem / EMB, n = rem % EMB;
        float w = (k < EMB) ? Wg[l][k * EMB + n] : Wb[l][(k - EMB) * EMB + n];
        g_wh[l][rem] = __float2half_rn(w);
    } else if (i < 3 * 128 * EMB + 3 * EMB) {
        int j = i - 3 * 128 * EMB;
        int l = j / EMB, n = j % EMB;
        g_bias[l][n] = bg[l][n] + bb[l][n];
    }
}

// ---------------- 3) output slice 0 (raw embeddings, gathered) -------------
__global__ void init_out(const int* __restrict__ users, const int* __restrict__ pos,
                         const int* __restrict__ neg,
                         const float* __restrict__ uemb, const float* __restrict__ iemb,
                         float* __restrict__ out) {
    int wid  = (blockIdx.x * blockDim.x + threadIdx.x) >> 5;
    int lane = threadIdx.x & 31;
    if (wid >= 3 * BATCH) return;
    int g = wid / BATCH, b = wid - g * BATCH;
    const float* src;
    if (g == 0)      src = uemb + (size_t)users[b] * EMB;
    else if (g == 1) src = iemb + (size_t)pos[b]   * EMB;
    else             src = iemb + (size_t)neg[b]   * EMB;
    float2 v = *reinterpret_cast<const float2*>(src + 2 * lane);
    *reinterpret_cast<float2*>(out + (size_t)wid * 256 + 2 * lane) = v;
}

// ---------------- 4) SpMM over fp16 ego; fp16 side/prod out ----------------
// Warp per row. Half-warp per nnz; lane owns a dim quad (LDG.64).
// Staged (val, col<<7): gather address is one IADD off a lane-base pointer.
__device__ __forceinline__ void fma_quad(float4& acc, float v, uint2 raw) {
    float2 f0 = __half22float2(*reinterpret_cast<half2*>(&raw.x));
    float2 f1 = __half22float2(*reinterpret_cast<half2*>(&raw.y));
    acc.x = fmaf(v, f0.x, acc.x); acc.y = fmaf(v, f0.y, acc.y);
    acc.z = fmaf(v, f1.x, acc.z); acc.w = fmaf(v, f1.y, acc.w);
}

__global__ void __launch_bounds__(256) spmm_kernel(
        const int* __restrict__ col, const float* __restrict__ val, int src) {
    __shared__ float2 stage[8][32];
    const char* __restrict__ egoB = (const char*)g_egoh[src];
    int w = threadIdx.x >> 5, lane = threadIdx.x & 31;
    int h = lane >> 4, q = lane & 15;          // half index, dim quad
    const char* laneB = egoB + 8 * q;          // byte base for this lane's quad
    int r = blockIdx.x * 8 + w;
    int beg = g_rowptr[r], end = g_rowptr[r + 1];
    float4 acc = make_float4(0.f, 0.f, 0.f, 0.f);

    for (int bs = beg; bs < end; bs += 32) {
        int i = bs + lane;
        if (i < end) stage[w][lane] = make_float2(val[i], __int_as_float(col[i] << 7));
        __syncwarp();
        int cnt = min(32, end - bs);
        int j = 0;
        for (; j + 16 <= cnt; j += 16) {       // 16 nnz, 8 LDG.64 in flight/half
            uint2 raw[8]; float v[8];
            #pragma unroll
            for (int t = 0; t < 8; t++) {
                float2 cv = stage[w][j + 2 * t + h];
                v[t] = cv.x;
                raw[t] = *reinterpret_cast<const uint2*>(laneB + __float_as_int(cv.y));
            }
            #pragma unroll
            for (int t = 0; t < 8; t++) fma_quad(acc, v[t], raw[t]);
        }
        for (; j + 2 <= cnt; j += 2) {
            float2 cv = stage[w][j + h];
            uint2 raw = *reinterpret_cast<const uint2*>(laneB + __float_as_int(cv.y));
            fma_quad(acc, cv.x, raw);
        }
        if (j < cnt && h == 0) {
            float2 cv = stage[w][j];
            uint2 raw = *reinterpret_cast<const uint2*>(laneB + __float_as_int(cv.y));
            fma_quad(acc, cv.x, raw);
        }
        __syncwarp();
    }
    acc.x += __shfl_xor_sync(0xffffffffu, acc.x, 16);
    acc.y += __shfl_xor_sync(0xffffffffu, acc.y, 16);
    acc.z += __shfl_xor_sync(0xffffffffu, acc.z, 16);
    acc.w += __shfl_xor_sync(0xffffffffu, acc.w, 16);

    if (h == 0) {                               // side (fp16)
        half2 h0 = __floats2half2_rn(acc.x, acc.y);
        half2 h1 = __floats2half2_rn(acc.z, acc.w);
        uint2 pk;
        pk.x = *reinterpret_cast<unsigned*>(&h0);
        pk.y = *reinterpret_cast<unsigned*>(&h1);
        *reinterpret_cast<uint2*>(g_sideh + (size_t)r * EMB + 4 * q) = pk;
    } else {                                    // prod = ego * side (fp16)
        uint2 raw = *reinterpret_cast<const uint2*>(egoB + ((size_t)r * EMB + 4 * q) * 2);
        float2 f0 = __half22float2(*reinterpret_cast<half2*>(&raw.x));
        float2 f1 = __half22float2(*reinterpret_cast<half2*>(&raw.y));
        half2 h0 = __floats2half2_rn(f0.x * acc.x, f0.y * acc.y);
        half2 h1 = __floats2half2_rn(f1.x * acc.z, f1.y * acc.w);
        uint2 pk;
        pk.x = *reinterpret_cast<unsigned*>(&h0);
        pk.y = *reinterpret_cast<unsigned*>(&h1);
        *reinterpret_cast<uint2*>(g_prodh + (size_t)r * EMB + 4 * q) = pk;
    }
}

// ---------------- 5) dense via HMMA: ego = leaky([side|prod]@Wcat + bias) --
__device__ __forceinline__ void ldsm_x4(unsigned& r0, unsigned& r1, unsigned& r2, unsigned& r3,
                                        unsigned addr) {
    asm volatile("ldmatrix.sync.aligned.m8n8.x4.shared.b16 {%0,%1,%2,%3}, [%4];"
                 : "=r"(r0), "=r"(r1), "=r"(r2), "=r"(r3) : "r"(addr));
}
__device__ __forceinline__ void ldsm_x4t(unsigned& r0, unsigned& r1, unsigned& r2, unsigned& r3,
                                         unsigned addr) {
    asm volatile("ldmatrix.sync.aligned.m8n8.x4.trans.shared.b16 {%0,%1,%2,%3}, [%4];"
                 : "=r"(r0), "=r"(r1), "=r"(r2), "=r"(r3) : "r"(addr));
}
__device__ __forceinline__ void mma16816(float* c, unsigned a0, unsigned a1, unsigned a2,
                                         unsigned a3, unsigned b0, unsigned b1) {
    asm volatile("mma.sync.aligned.m16n8k16.row.col.f32.f16.f16.f32 "
                 "{%0,%1,%2,%3},{%4,%5,%6,%7},{%8,%9},{%0,%1,%2,%3};"
                 : "+f"(c[0]), "+f"(c[1]), "+f"(c[2]), "+f"(c[3])
                 : "r"(a0), "r"(a1), "r"(a2), "r"(a3), "r"(b0), "r"(b1));
}

// Block: 128 rows, 256 threads (8 warps). Warp w owns m-tile rows [16w,16w+16).
// A: [128 rows][16 chunks of 16B] (side chunks 0-7, prod 8-15), swizzled c^=(row&7).
// B: [128 k][8 chunks of 16B], swizzled. K-loop of 8 x m16n8k16 per n-tile.
__global__ void __launch_bounds__(256) dense_kernel(int layer, int dst) {
    __shared__ __align__(16) char sA[128 * 256];   // 32 KB
    __shared__ __align__(16) char sB[128 * 128];   // 16 KB
    float*  __restrict__ ego_next  = g_ego[dst];
    __half* __restrict__ egoh_next = g_egoh[dst];
    int tid = threadIdx.x, w = tid >> 5, lane = tid & 31;
    int rowbase = blockIdx.x * 128;

    // ---- stage A (side, prod) with swizzle
    {
        const uint4* gs = reinterpret_cast<const uint4*>(g_sideh + (size_t)rowbase * EMB);
        const uint4* gp = reinterpret_cast<const uint4*>(g_prodh + (size_t)rowbase * EMB);
        #pragma unroll
        for (int i = 0; i < 4; i++) {
            int id = tid + i * 256;               // 1024 chunks each
            int row = id >> 3, c = id & 7;
            bool ok = rowbase + row < N_NODES;
            uint4 vs = ok ? gs[id] : make_uint4(0, 0, 0, 0);
            uint4 vp = ok ? gp[id] : make_uint4(0, 0, 0, 0);
            *reinterpret_cast<uint4*>(sA + row * 256 + ((c       ^ (row & 7)) << 4)) = vs;
            *reinterpret_cast<uint4*>(sA + row * 256 + (((8 + c) ^ (row & 7)) << 4)) = vp;
        }
        const uint4* gw = reinterpret_cast<const uint4*>(g_wh[layer]);
        #pragma unroll
        for (int i = 0; i < 4; i++) {
            int id = tid + i * 256;               // 1024 chunks
            int row = id >> 3, c = id & 7;
            *reinterpret_cast<uint4*>(sB + row * 128 + ((c ^ (row & 7)) << 4)) = gw[id];
        }
    }
    __syncthreads();

    unsigned aBase = (unsigned)__cvta_generic_to_shared(sA);
    unsigned bBase = (unsigned)__cvta_generic_to_shared(sB);

    float acc[8][4];
    #pragma unroll
    for (int j = 0; j < 8; j++)
        #pragma unroll
        for (int t = 0; t < 4; t++) acc[j][t] = 0.f;

    // A address: row = w*16 + (lane&15); chunk = 2*kt + (lane>>4); phys = chunk^(lane&7)
    int aRow = w * 16 + (lane & 15);
    // B address: row = 16*kt + (lane&7) + ((lane>>3)&1)*8; chunk = j0 + (lane>>4)
    int bRowLocal = (lane & 7) + ((lane >> 3) & 1) * 8;

    #pragma unroll
    for (int kt = 0; kt < 8; kt++) {
        unsigned a0, a1, a2, a3;
        {
            int c = 2 * kt + (lane >> 4);
            unsigned addr = aBase + aRow * 256 + ((c ^ (lane & 7)) << 4);
            ldsm_x4(a0, a1, a2, a3, addr);
        }
        unsigned b[8][2];
        #pragma unroll
        for (int g = 0; g < 4; g++) {           // n-tiles 2g, 2g+1
            int row = 16 * kt + bRowLocal;
            int c = 2 * g + (lane >> 4);
            unsigned addr = bBase + row * 128 + ((c ^ (lane & 7)) << 4);
            ldsm_x4t(b[2 * g][0], b[2 * g][1], b[2 * g + 1][0], b[2 * g + 1][1], addr);
        }
        #pragma unroll
        for (int j = 0; j < 8; j++)
            mma16816(acc[j], a0, a1, a2, a3, b[j][0], b[j][1]);
    }

    // ---- epilogue: bias + leaky relu, write fp32 + fp16 ego
    int r0 = rowbase + w * 16 + (lane >> 2);
    int r1 = r0 + 8;
    int cbase = 2 * (lane & 3);
    const float* bias = g_bias[layer];
    #pragma unroll
    for (int j = 0; j < 8; j++) {
        int colv = 8 * j + cbase;
        float2 bj = *reinterpret_cast<const float2*>(bias + colv);
        float x0 = acc[j][0] + bj.x, y0 = acc[j][1] + bj.y;
        float x1 = acc[j][2] + bj.x, y1 = acc[j][3] + bj.y;
        x0 = x0 > 0.f ? x0 : 0.2f * x0;  y0 = y0 > 0.f ? y0 : 0.2f * y0;
        x1 = x1 > 0.f ? x1 : 0.2f * x1;  y1 = y1 > 0.f ? y1 : 0.2f * y1;
        if (r0 < N_NODES) {
            size_t o = (size_t)r0 * EMB + colv;
            *reinterpret_cast<float2*>(ego_next + o) = make_float2(x0, y0);
            *reinterpret_cast<half2*>(egoh_next + o) = __floats2half2_rn(x0, y0);
        }
        if (r1 < N_NODES) {
            size_t o = (size_t)r1 * EMB + colv;
            *reinterpret_cast<float2*>(ego_next + o) = make_float2(x1, y1);
            *reinterpret_cast<half2*>(egoh_next + o) = __floats2half2_rn(x1, y1);
        }
    }
}

// ---------------- 6) per-layer gather + l2norm straight into d_out ---------
__global__ void gather_norm(const int* __restrict__ users, const int* __restrict__ pos,
                            const int* __restrict__ neg, int src, float* __restrict__ out,
                            int slice) {
    const float* __restrict__ ego = g_ego[src];
    int wid  = (blockIdx.x * blockDim.x + threadIdx.x) >> 5;
    int lane = threadIdx.x & 31;
    if (wid >= 3 * BATCH) return;
    int g = wid / BATCH, b = wid - g * BATCH;
    int node;
    if (g == 0)      node = users[b];
    else if (g == 1) node = N_USER + pos[b];
    else             node = N_USER + neg[b];
    float2 v = *reinterpret_cast<const float2*>(ego + (size_t)node * EMB + 2 * lane);
    float ss = v.x * v.x + v.y * v.y;
    #pragma unroll
    for (int o = 16; o; o >>= 1) ss += __shfl_xor_sync(0xffffffffu, ss, o);
    float n = sqrtf(ss);
    float inv = 1.f / fmaxf(n, 1e-12f);
    *reinterpret_cast<float2*>(out + (size_t)wid * 256 + slice * EMB + 2 * lane)
        = make_float2(v.x * inv, v.y * inv);
}

// ---------------- launch ---------------------------------------------------
extern "C" void kernel_launch(void* const* d_in, const int* in_sizes, int n_in,
                              void* d_out, int out_size) {
    const int*   users = (const int*)  d_in[0];
    const int*   pos   = (const int*)  d_in[1];
    const int*   neg   = (const int*)  d_in[2];
    const int*   arow  = (const int*)  d_in[3];
    const int*   acol  = (const int*)  d_in[4];
    const float* aval  = (const float*)d_in[5];
    const float* uemb  = (const float*)d_in[6];
    const float* iemb  = (const float*)d_in[7];
    float* out = (float*)d_out;

    build_rowptr<<<(N_NODES + 256) / 256, 256>>>(arow);
    conv_ego0<<<(N_NODES * EMB / 4 + 255) / 256, 256>>>(
        (const float4*)uemb, (const float4*)iemb);
    conv_weights<<<(3 * 128 * EMB + 3 * EMB + 255) / 256, 256>>>(
        (const float*)d_in[8],  (const float*)d_in[10], (const float*)d_in[9],  (const float*)d_in[11],
        (const float*)d_in[12], (const float*)d_in[14], (const float*)d_in[13], (const float*)d_in[15],
        (const float*)d_in[16], (const float*)d_in[18], (const float*)d_in[17], (const float*)d_in[19]);
    init_out<<<(3 * BATCH * 32) / 256, 256>>>(users, pos, neg, uemb, iemb, out);

    const int DBLK = (N_NODES + 127) / 128;

    // layer 0: egoh[0] -> ego/egoh[1]
    spmm_kernel<<<N_NODES / 8, 256>>>(acol, aval, 0);
    dense_kernel<<<DBLK, 256>>>(0, 1);
    gather_norm<<<(3 * BATCH * 32) / 256, 256>>>(users, pos, neg, 1, out, 1);

    // layer 1: egoh[1] -> ego/egoh[0]
    spmm_kernel<<<N_NODES / 8, 256>>>(acol, aval, 1);
    dense_kernel<<<DBLK, 256>>>(1, 0);
    gather_norm<<<(3 * BATCH * 32) / 256, 256>>>(users, pos, neg, 0, out, 2);

    // layer 2: egoh[0] -> ego/egoh[1]
    spmm_kernel<<<N_NODES / 8, 256>>>(acol, aval, 0);
    dense_kernel<<<DBLK, 256>>>(2, 1);
    gather_norm<<<(3 * BATCH * 32) / 256, 256>>>(users, pos, neg, 1, out, 3);
}